// round 10
// baseline (speedup 1.0000x reference)
#include <cuda_runtime.h>
#include <math.h>

#define N_NODES  50000
#define N_EDGES  800000
#define N_GRAPHS 512
#define IN_F     128
#define HEADS    8
#define OUT_F    64
#define NEG_SLOPE 0.2f
#define SCAN_BLOCKS 49   // ceil(50000/1024)
#define SCAN_THREADS (SCAN_BLOCKS * 1024)

// ---------------- scratch (BSS zero-initialized at load) ----------------
__device__ __align__(16) float g_h   [N_NODES * OUT_F];   // 12.8 MB
__device__ __align__(16) float g_as  [N_NODES * HEADS];
__device__ __align__(16) float g_ad  [N_NODES * HEADS];
__device__ __align__(16) float g_p   [N_NODES];
__device__ __align__(16) float g_score[N_NODES];
__device__ __align__(16) float g_gden [N_GRAPHS];
__device__ int g_batch[N_NODES];
__device__ int g_cnt  [N_NODES];        // zeroed by k_scanAF after use (and BSS initially)
__device__ int g_bsum [SCAN_BLOCKS];
__device__ int g_bbase[SCAN_BLOCKS];
__device__ int g_offs [N_NODES + 1];
__device__ int g_cursor[N_NODES];
__device__ int g_csr  [N_EDGES];
__device__ int g_t1, g_t2, g_ready;     // scanAF barrier state; reset by k10

// ---------------- helpers ----------------
__device__ __forceinline__ float lrelu(float v) { return v > 0.f ? v : NEG_SLOPE * v; }

__device__ __forceinline__ void red_add_v4(float* addr, float4 v) {
    asm volatile("red.global.add.v4.f32 [%0], {%1,%2,%3,%4};"
                 :: "l"(addr), "f"(v.x), "f"(v.y), "f"(v.z), "f"(v.w) : "memory");
}

__device__ __forceinline__ int detect_e64(const void* ei) {
    const long long* e64 = (const long long*)ei;
    int ok = 1;
    #pragma unroll
    for (int i = 0; i < 16; i++) {
        long long v = e64[(long long)i * 49999 + 3];
        if (v < 0 || v >= N_NODES) ok = 0;
    }
    return ok;
}
__device__ __forceinline__ int detect_b64(const void* batch) {
    const long long* b64 = (const long long*)batch;
    int ok = 1;
    #pragma unroll
    for (int i = 0; i < 16; i++) {
        long long v = b64[(long long)i * 1499 + 11];
        if (v < 0 || v >= N_GRAPHS) ok = 0;
    }
    return ok;
}

// ---------------- K_hist: batch convert + gout/gden init + dst histogram ----------------
// g_cnt arrives already zeroed (BSS first run; k_scanAF re-zeroes for replays).
__global__ void k_hist(const void* ei, const void* batch, float* __restrict__ gout)
{
    __shared__ int se, sb;
    int tid = threadIdx.x;
    if (tid == 0) { se = detect_e64(ei); sb = detect_b64(batch); }
    __syncthreads();
    int i = blockIdx.x * 256 + tid;
    if (i < N_NODES) {
        if (sb) g_batch[i] = (int)((const long long*)batch)[i];
        else    g_batch[i] = ((const int*)batch)[i];
    }
    if (i < N_GRAPHS * OUT_F) gout[i] = 0.f;
    if (i < N_GRAPHS) g_gden[i] = 0.f;
    if (i < N_EDGES) {
        int d;
        if (se) d = (int)((const long long*)ei)[N_EDGES + i];
        else    d = ((const int*)ei)[N_EDGES + i];
        atomicAdd(&g_cnt[d], 1);
    }
}

// ---------------- K_scanAF: scan + offs/cursor + cnt re-zero + CSR fill ----------------
// 49 blocks x 1024 threads: all resident in wave 1, grid-wide spin barriers safe.
__global__ void __launch_bounds__(1024) k_scanAF(const void* ei)
{
    __shared__ int sdata[1024];
    __shared__ int sbase;
    __shared__ int s_se;
    int tid = threadIdx.x;
    int idx = blockIdx.x * 1024 + tid;

    int v = (idx < N_NODES) ? g_cnt[idx] : 0;
    if (idx < N_NODES) g_cnt[idx] = 0;       // restore zero-state for next replay
    sdata[tid] = v;
    __syncthreads();
    #pragma unroll
    for (int off = 1; off < 1024; off <<= 1) {
        int t = (tid >= off) ? sdata[tid - off] : 0;
        __syncthreads();
        sdata[tid] += t;
        __syncthreads();
    }

    // phase 1: block sums -> bases (last-arriving block computes all 49)
    if (tid == 0) {
        g_bsum[blockIdx.x] = sdata[1023];
        __threadfence();
        int done = atomicAdd(&g_t1, 1);
        if (done == SCAN_BLOCKS - 1) {
            int run = 0;
            #pragma unroll 1
            for (int b = 0; b < SCAN_BLOCKS; b++) { g_bbase[b] = run; run += g_bsum[b]; }
            __threadfence();
            atomicExch(&g_ready, 1);
        }
        while (atomicAdd(&g_ready, 0) == 0) __nanosleep(64);
        __threadfence();
        sbase = g_bbase[blockIdx.x];
        s_se  = detect_e64(ei);
    }
    __syncthreads();

    if (idx < N_NODES) {
        int excl = sdata[tid] - v + sbase;
        g_offs[idx]   = excl;
        g_cursor[idx] = excl;
    }
    if (idx == 0) g_offs[N_NODES] = N_EDGES;

    // phase 2: all cursors visible before anyone fills
    __threadfence();
    __syncthreads();
    if (tid == 0) {
        atomicAdd(&g_t2, 1);
        while (atomicAdd(&g_t2, 0) < SCAN_BLOCKS) __nanosleep(64);
        __threadfence();
    }
    __syncthreads();

    // fill phase: grid-strided over edges
    int se = s_se;
    for (int e = idx; e < N_EDGES; e += SCAN_THREADS) {
        int s, d;
        if (se) {
            const long long* e64 = (const long long*)ei;
            s = (int)e64[e];
            d = (int)e64[N_EDGES + e];
        } else {
            const int* e32 = (const int*)ei;
            s = e32[e];
            d = e32[N_EDGES + e];
        }
        int pos = atomicAdd(&g_cursor[d], 1);
        g_csr[pos] = s;
    }
}

// ---------------- K1: tiled GEMM + fused attention logits ----------------
#define XPITCH 68
__global__ void k1_gemm(const float* __restrict__ x, const float* __restrict__ W,
                        const float* __restrict__ att_src, const float* __restrict__ att_dst)
{
    __shared__ float sx[32 * XPITCH];
    __shared__ float sw[32 * OUT_F];
    int tid  = threadIdx.x;
    int tcol = tid & 15;
    int trow = tid >> 4;
    int nb   = blockIdx.x * 64;

    float acc[4][4];
    #pragma unroll
    for (int i = 0; i < 4; i++)
        #pragma unroll
        for (int j = 0; j < 4; j++) acc[i][j] = 0.f;

    for (int k0 = 0; k0 < IN_F; k0 += 32) {
        #pragma unroll
        for (int r = 0; r < 2; r++) {
            int j = r * 256 + tid;
            int k = j >> 4, c4 = j & 15;
            *(float4*)&sw[k * OUT_F + c4 * 4] = *(const float4*)&W[(k0 + k) * OUT_F + c4 * 4];
        }
        #pragma unroll
        for (int r = 0; r < 2; r++) {
            int j = r * 256 + tid;
            int n = j >> 3, kq = j & 7;
            int node = nb + n; if (node >= N_NODES) node = N_NODES - 1;
            float4 xv = *(const float4*)&x[(long)node * IN_F + k0 + kq * 4];
            sx[(kq * 4 + 0) * XPITCH + n] = xv.x;
            sx[(kq * 4 + 1) * XPITCH + n] = xv.y;
            sx[(kq * 4 + 2) * XPITCH + n] = xv.z;
            sx[(kq * 4 + 3) * XPITCH + n] = xv.w;
        }
        __syncthreads();
        #pragma unroll
        for (int kk = 0; kk < 32; kk++) {
            float4 xv = *(const float4*)&sx[kk * XPITCH + trow * 4];
            float4 wv = *(const float4*)&sw[kk * OUT_F + tcol * 4];
            float xr[4] = {xv.x, xv.y, xv.z, xv.w};
            float wr[4] = {wv.x, wv.y, wv.z, wv.w};
            #pragma unroll
            for (int i = 0; i < 4; i++)
                #pragma unroll
                for (int j = 0; j < 4; j++)
                    acc[i][j] = fmaf(xr[i], wr[j], acc[i][j]);
        }
        __syncthreads();
    }

    float4 asv = *(const float4*)&att_src[tcol * 4];
    float4 adv = *(const float4*)&att_dst[tcol * 4];
    #pragma unroll
    for (int i = 0; i < 4; i++) {
        int node = nb + trow * 4 + i;
        if (node >= N_NODES) continue;
        float4 v = make_float4(acc[i][0], acc[i][1], acc[i][2], acc[i][3]);
        *(float4*)&g_h[(long)node * OUT_F + tcol * 4] = v;

        float vs = v.x * asv.x + v.y * asv.y + v.z * asv.z + v.w * asv.w;
        float vd = v.x * adv.x + v.y * adv.y + v.z * adv.z + v.w * adv.w;
        vs += __shfl_xor_sync(0xffffffffu, vs, 1);
        vd += __shfl_xor_sync(0xffffffffu, vd, 1);
        if ((tcol & 1) == 0) {
            int head = tcol >> 1;
            g_as[node * 8 + head] = vs;
            g_ad[node * 8 + head] = vd;
        }
    }
}

// ---------------- K_agg: fused softmax + aggregation + score projections ----------------
// lane handles columns (2*lane, 2*lane+1) -> head = lane>>2
__global__ void k_agg(float* __restrict__ out, const float* __restrict__ bias,
                      const float* __restrict__ wrel, const float* __restrict__ brel,
                      const float* __restrict__ wroot)
{
    int warp = threadIdx.x >> 5, lane = threadIdx.x & 31;
    int n = blockIdx.x * 8 + warp;
    if (n >= N_NODES) return;
    int head = lane >> 2;
    int c2   = lane * 2;

    float ad = g_ad[n * 8 + head];

    float exs = __expf(lrelu(g_as[n * 8 + head] + ad));
    float den = exs;
    float2 hv = *(const float2*)&g_h[n * 64 + c2];
    float acc0 = exs * hv.x;
    float acc1 = exs * hv.y;

    int beg = g_offs[n], end = g_offs[n + 1];
    int j = beg;
    for (; j + 7 < end; j += 8) {
        int s[8];
        #pragma unroll
        for (int u = 0; u < 8; u++) s[u] = g_csr[j + u];
        float a[8]; float2 hh[8];
        #pragma unroll
        for (int u = 0; u < 8; u++) {
            a[u]  = g_as[s[u] * 8 + head];
            hh[u] = *(const float2*)&g_h[s[u] * 64 + c2];
        }
        #pragma unroll
        for (int u = 0; u < 8; u++) {
            float e = __expf(lrelu(a[u] + ad));
            den += e;
            acc0 = fmaf(e, hh[u].x, acc0);
            acc1 = fmaf(e, hh[u].y, acc1);
        }
    }
    for (; j < end; j++) {
        int s = g_csr[j];
        float e = __expf(lrelu(g_as[s * 8 + head] + ad));
        den += e;
        float2 h2 = *(const float2*)&g_h[s * 64 + c2];
        acc0 = fmaf(e, h2.x, acc0);
        acc1 = fmaf(e, h2.y, acc1);
    }

    float inv = 1.f / (den + 1e-16f);
    float o0 = bias[c2]     + acc0 * inv;
    float o1 = bias[c2 + 1] + acc1 * inv;
    *(float2*)&out[n * 64 + c2] = make_float2(o0, o1);

    float vr = o0 * wrel[c2]  + o1 * wrel[c2 + 1];
    float vq = o0 * wroot[c2] + o1 * wroot[c2 + 1];
    #pragma unroll
    for (int off = 16; off; off >>= 1) {
        vr += __shfl_xor_sync(0xffffffffu, vr, off);
        vq += __shfl_xor_sync(0xffffffffu, vq, off);
    }
    if (lane == 0) {
        g_p[n]     = vr;
        g_score[n] = brel[0] + vq;
    }
}

// ---------------- K7: score aggregation via CSR + fused exp/gden ----------------
__global__ void k7_score_gexp()
{
    int warp = threadIdx.x >> 5, lane = threadIdx.x & 31;
    int n = blockIdx.x * 8 + warp;
    if (n >= N_NODES) return;
    int beg = g_offs[n], end = g_offs[n + 1];
    float acc = 0.f;
    for (int j = beg + lane; j < end; j += 32) acc += g_p[g_csr[j]];
    #pragma unroll
    for (int off = 16; off; off >>= 1) acc += __shfl_xor_sync(0xffffffffu, acc, off);
    if (lane == 0) {
        float ex = __expf(g_score[n] + acc);   // scores O(±10): unshifted exp safe
        g_score[n] = ex;
        atomicAdd(&g_gden[g_batch[n]], ex);
    }
}

// ---------------- K10: pooled output + barrier-state reset ----------------
__global__ void k10_gpool(const float* __restrict__ out, float* __restrict__ gout)
{
    int t = blockIdx.x * blockDim.x + threadIdx.x;   // 100000 threads
    if (t == 0) { g_t1 = 0; g_t2 = 0; g_ready = 0; } // reset scanAF barriers for next replay
    if (t >= 100000) return;
    int q   = t & 15;
    int n0  = (t >> 4) * 8;

    float4 acc = make_float4(0.f, 0.f, 0.f, 0.f);
    int curg = g_batch[n0];
    float inv = 1.f / (g_gden[curg] + 1e-16f);
    #pragma unroll
    for (int i = 0; i < 8; i++) {
        int n = n0 + i;
        int g = g_batch[n];
        if (g != curg) {
            red_add_v4(&gout[curg * 64 + q * 4], acc);
            acc = make_float4(0.f, 0.f, 0.f, 0.f);
            curg = g;
            inv = 1.f / (g_gden[curg] + 1e-16f);
        }
        float s = g_score[n] * inv;
        float4 v = *(const float4*)&out[(long)n * 64 + q * 4];
        acc.x = fmaf(v.x, s, acc.x);
        acc.y = fmaf(v.y, s, acc.y);
        acc.z = fmaf(v.z, s, acc.z);
        acc.w = fmaf(v.w, s, acc.w);
    }
    red_add_v4(&gout[curg * 64 + q * 4], acc);
}

// ---------------- launch ----------------
extern "C" void kernel_launch(void* const* d_in, const int* in_sizes, int n_in,
                              void* d_out, int out_size)
{
    const float* x = 0; const void* ei = 0; const void* batch = 0;
    const float* W = 0; const float* brel = 0;
    const float* f64s[5] = {0,0,0,0,0};
    int n64 = 0;
    for (int i = 0; i < n_in; i++) {
        long long sz = in_sizes[i];
        if      (sz == (long long)N_NODES * IN_F) x     = (const float*)d_in[i];
        else if (sz == (long long)2 * N_EDGES)    ei    = d_in[i];
        else if (sz == N_NODES)                   batch = d_in[i];
        else if (sz == IN_F * OUT_F)              W     = (const float*)d_in[i];
        else if (sz == 1)                         brel  = (const float*)d_in[i];
        else if (sz == OUT_F && n64 < 5)          f64s[n64++] = (const float*)d_in[i];
    }
    const float* asrc  = f64s[0];
    const float* adst  = f64s[1];
    const float* bias  = f64s[2];
    const float* wrel  = f64s[3];
    const float* wroot = f64s[4];

    float* out  = (float*)d_out;
    float* gout = out + (long)N_NODES * OUT_F;

    k_hist<<<(N_EDGES + 255) / 256, 256>>>(ei, batch, gout);     // 1
    k_scanAF<<<SCAN_BLOCKS, 1024>>>(ei);                          // 2
    k1_gemm<<<(N_NODES + 63) / 64, 256>>>(x, W, asrc, adst);      // 3
    k_agg<<<(N_NODES + 7) / 8, 256>>>(out, bias, wrel, brel, wroot); // 4 <- ncu capture slot
    k7_score_gexp<<<(N_NODES + 7) / 8, 256>>>();                  // 5
    k10_gpool<<<(100000 + 255) / 256, 256>>>(out, gout);          // 6
}

// round 13
// speedup vs baseline: 1.1369x; 1.1369x over previous
#include <cuda_runtime.h>
#include <math.h>

#define N_NODES  50000
#define N_EDGES  800000
#define N_GRAPHS 512
#define IN_F     128
#define HEADS    8
#define OUT_F    64
#define NEG_SLOPE 0.2f
#define SCAN_BLOCKS 49   // ceil(50000/1024)

// ---------------- scratch ----------------
__device__ __align__(16) float g_h   [N_NODES * OUT_F];   // 12.8 MB
__device__ __align__(16) float g_as  [N_NODES * HEADS];
__device__ __align__(16) float g_ad  [N_NODES * HEADS];
__device__ __align__(16) float g_p   [N_NODES];
__device__ __align__(16) float g_score[N_NODES];
__device__ __align__(16) float g_gden [N_GRAPHS];
__device__ int g_batch[N_NODES];
__device__ int g_cnt  [N_NODES];
__device__ int g_incl [SCAN_BLOCKS * 1024];
__device__ int g_bsum [SCAN_BLOCKS];
__device__ int g_bbase[SCAN_BLOCKS];
__device__ int g_offs [N_NODES + 1];
__device__ int g_cursor[N_NODES];
__device__ int g_csr  [N_EDGES];
__device__ int g_eflag;
__device__ int g_scan_done;

// ---------------- helpers ----------------
__device__ __forceinline__ float lrelu(float v) { return fmaxf(v, NEG_SLOPE * v); }

__device__ __forceinline__ void red_add_v4(float* addr, float4 v) {
    asm volatile("red.global.add.v4.f32 [%0], {%1,%2,%3,%4};"
                 :: "l"(addr), "f"(v.x), "f"(v.y), "f"(v.z), "f"(v.w) : "memory");
}

__device__ __forceinline__ int detect_e64(const void* ei) {
    const long long* e64 = (const long long*)ei;
    int ok = 1;
    #pragma unroll
    for (int i = 0; i < 16; i++) {
        long long v = e64[(long long)i * 49999 + 3];
        if (v < 0 || v >= N_NODES) ok = 0;
    }
    return ok;
}
__device__ __forceinline__ int detect_b64(const void* batch) {
    const long long* b64 = (const long long*)batch;
    int ok = 1;
    #pragma unroll
    for (int i = 0; i < 16; i++) {
        long long v = b64[(long long)i * 1499 + 11];
        if (v < 0 || v >= N_GRAPHS) ok = 0;
    }
    return ok;
}

// ---------------- K0: node init ----------------
__global__ void k0_nodes(const void* batch)
{
    __shared__ int sb;
    int tid = threadIdx.x;
    if (tid == 0) {
        sb = detect_b64(batch);
        if (blockIdx.x == 0) g_scan_done = 0;
    }
    __syncthreads();
    int i = blockIdx.x * 256 + tid;
    if (i >= N_NODES) return;
    g_cnt[i] = 0;
    if (sb) g_batch[i] = (int)((const long long*)batch)[i];
    else    g_batch[i] = ((const int*)batch)[i];
}

// ---------------- K_hist: dst histogram ----------------
__global__ void k_hist(const void* ei)
{
    __shared__ int se;
    int tid = threadIdx.x;
    if (tid == 0) {
        se = detect_e64(ei);
        if (blockIdx.x == 0) g_eflag = se;
    }
    __syncthreads();
    int i = blockIdx.x * 256 + tid;
    if (i >= N_EDGES) return;
    int d;
    if (se) d = (int)((const long long*)ei)[N_EDGES + i];
    else    d = ((const int*)ei)[N_EDGES + i];
    atomicAdd(&g_cnt[d], 1);
}

// ---------------- K_scan1 ----------------
__global__ void k_scan1()
{
    __shared__ int sdata[1024];
    __shared__ int is_last;
    int tid = threadIdx.x;
    int idx = blockIdx.x * 1024 + tid;
    int v = (idx < N_NODES) ? g_cnt[idx] : 0;
    sdata[tid] = v;
    __syncthreads();
    #pragma unroll
    for (int off = 1; off < 1024; off <<= 1) {
        int t = (tid >= off) ? sdata[tid - off] : 0;
        __syncthreads();
        sdata[tid] += t;
        __syncthreads();
    }
    g_incl[idx] = sdata[tid];

    if (tid == 0) {
        g_bsum[blockIdx.x] = sdata[1023];
        __threadfence();
        int done = atomicAdd(&g_scan_done, 1);
        is_last = (done == SCAN_BLOCKS - 1);
    }
    __syncthreads();
    if (is_last) {
        int val = (tid < SCAN_BLOCKS) ? g_bsum[tid] : 0;
        sdata[tid] = (tid < 64) ? val : 0;
        __syncthreads();
        #pragma unroll
        for (int off = 1; off < 64; off <<= 1) {
            int t = (tid >= off && tid < 64) ? sdata[tid - off] : 0;
            __syncthreads();
            if (tid < 64) sdata[tid] += t;
            __syncthreads();
        }
        if (tid < SCAN_BLOCKS) g_bbase[tid] = sdata[tid] - val;
    }
}

// ---------------- K_scan3 ----------------
__global__ void k_scan3(float* __restrict__ gout)
{
    int idx = blockIdx.x * blockDim.x + threadIdx.x;
    if (idx < N_GRAPHS * OUT_F) gout[idx] = 0.f;
    if (idx < N_GRAPHS) g_gden[idx] = 0.f;
    if (idx >= N_NODES) return;
    int excl = g_incl[idx] - g_cnt[idx] + g_bbase[idx >> 10];
    g_offs[idx]   = excl;
    g_cursor[idx] = excl;
    if (idx == 0) g_offs[N_NODES] = N_EDGES;
}

// ---------------- K_fill ----------------
__global__ void k_fill(const void* ei)
{
    int e = blockIdx.x * blockDim.x + threadIdx.x;
    if (e >= N_EDGES) return;
    int s, d;
    if (g_eflag) {
        const long long* e64 = (const long long*)ei;
        s = (int)e64[e];
        d = (int)e64[N_EDGES + e];
    } else {
        const int* e32 = (const int*)ei;
        s = e32[e];
        d = e32[N_EDGES + e];
    }
    int pos = atomicAdd(&g_cursor[d], 1);
    g_csr[pos] = s;
}

// ---------------- K1: tiled GEMM + fused attention logits ----------------
#define XPITCH 68
__global__ void k1_gemm(const float* __restrict__ x, const float* __restrict__ W,
                        const float* __restrict__ att_src, const float* __restrict__ att_dst)
{
    __shared__ float sx[32 * XPITCH];
    __shared__ float sw[32 * OUT_F];
    int tid  = threadIdx.x;
    int tcol = tid & 15;
    int trow = tid >> 4;
    int nb   = blockIdx.x * 64;

    float acc[4][4];
    #pragma unroll
    for (int i = 0; i < 4; i++)
        #pragma unroll
        for (int j = 0; j < 4; j++) acc[i][j] = 0.f;

    for (int k0 = 0; k0 < IN_F; k0 += 32) {
        #pragma unroll
        for (int r = 0; r < 2; r++) {
            int j = r * 256 + tid;
            int k = j >> 4, c4 = j & 15;
            *(float4*)&sw[k * OUT_F + c4 * 4] = *(const float4*)&W[(k0 + k) * OUT_F + c4 * 4];
        }
        #pragma unroll
        for (int r = 0; r < 2; r++) {
            int j = r * 256 + tid;
            int n = j >> 3, kq = j & 7;
            int node = nb + n; if (node >= N_NODES) node = N_NODES - 1;
            float4 xv = *(const float4*)&x[(long)node * IN_F + k0 + kq * 4];
            sx[(kq * 4 + 0) * XPITCH + n] = xv.x;
            sx[(kq * 4 + 1) * XPITCH + n] = xv.y;
            sx[(kq * 4 + 2) * XPITCH + n] = xv.z;
            sx[(kq * 4 + 3) * XPITCH + n] = xv.w;
        }
        __syncthreads();
        #pragma unroll
        for (int kk = 0; kk < 32; kk++) {
            float4 xv = *(const float4*)&sx[kk * XPITCH + trow * 4];
            float4 wv = *(const float4*)&sw[kk * OUT_F + tcol * 4];
            float xr[4] = {xv.x, xv.y, xv.z, xv.w};
            float wr[4] = {wv.x, wv.y, wv.z, wv.w};
            #pragma unroll
            for (int i = 0; i < 4; i++)
                #pragma unroll
                for (int j = 0; j < 4; j++)
                    acc[i][j] = fmaf(xr[i], wr[j], acc[i][j]);
        }
        __syncthreads();
    }

    float4 asv = *(const float4*)&att_src[tcol * 4];
    float4 adv = *(const float4*)&att_dst[tcol * 4];
    #pragma unroll
    for (int i = 0; i < 4; i++) {
        int node = nb + trow * 4 + i;
        if (node >= N_NODES) continue;
        float4 v = make_float4(acc[i][0], acc[i][1], acc[i][2], acc[i][3]);
        *(float4*)&g_h[(long)node * OUT_F + tcol * 4] = v;

        float vs = v.x * asv.x + v.y * asv.y + v.z * asv.z + v.w * asv.w;
        float vd = v.x * adv.x + v.y * adv.y + v.z * adv.z + v.w * adv.w;
        vs += __shfl_xor_sync(0xffffffffu, vs, 1);
        vd += __shfl_xor_sync(0xffffffffu, vd, 1);
        if ((tcol & 1) == 0) {
            int head = tcol >> 1;
            g_as[node * 8 + head] = vs;
            g_ad[node * 8 + head] = vd;
        }
    }
}

// ---------------- K_agg: half-warp x float4 — 2 edges per warp instruction ----------------
// half h in {0,1} takes alternate edges; lane covers 4 columns; head=(lane&15)>>1.
__global__ void k_agg(float* __restrict__ out, const float* __restrict__ bias,
                      const float* __restrict__ wrel, const float* __restrict__ brel,
                      const float* __restrict__ wroot)
{
    int warp = threadIdx.x >> 5, lane = threadIdx.x & 31;
    int n = blockIdx.x * 8 + warp;
    if (n >= N_NODES) return;
    int half = lane >> 4;       // 0 or 1
    int hl   = lane & 15;       // 0..15
    int head = hl >> 1;         // 0..7
    int c4   = hl * 4;          // column base

    float ad = g_ad[n * 8 + head];

    float den = 0.f;
    float4 acc = make_float4(0.f, 0.f, 0.f, 0.f);

    if (half == 0) {   // self-loop handled once, by half 0
        float e = __expf(lrelu(g_as[n * 8 + head] + ad));
        den = e;
        float4 hv = *(const float4*)&g_h[n * 64 + c4];
        acc.x = e * hv.x; acc.y = e * hv.y; acc.z = e * hv.z; acc.w = e * hv.w;
    }

    int beg = g_offs[n], end = g_offs[n + 1];
    int j = beg + half;
    // 4-per-half unroll: 8 edges per warp iteration
    for (; j + 6 < end; j += 8) {
        int s0 = g_csr[j];
        int s1 = g_csr[j + 2];
        int s2 = g_csr[j + 4];
        int s3 = g_csr[j + 6];
        float a0 = g_as[s0 * 8 + head];
        float a1 = g_as[s1 * 8 + head];
        float a2 = g_as[s2 * 8 + head];
        float a3 = g_as[s3 * 8 + head];
        float4 h0 = *(const float4*)&g_h[s0 * 64 + c4];
        float4 h1 = *(const float4*)&g_h[s1 * 64 + c4];
        float4 h2 = *(const float4*)&g_h[s2 * 64 + c4];
        float4 h3 = *(const float4*)&g_h[s3 * 64 + c4];
        float e0 = __expf(lrelu(a0 + ad));
        float e1 = __expf(lrelu(a1 + ad));
        float e2 = __expf(lrelu(a2 + ad));
        float e3 = __expf(lrelu(a3 + ad));
        den += (e0 + e1) + (e2 + e3);
        acc.x = fmaf(e0, h0.x, fmaf(e1, h1.x, fmaf(e2, h2.x, fmaf(e3, h3.x, acc.x))));
        acc.y = fmaf(e0, h0.y, fmaf(e1, h1.y, fmaf(e2, h2.y, fmaf(e3, h3.y, acc.y))));
        acc.z = fmaf(e0, h0.z, fmaf(e1, h1.z, fmaf(e2, h2.z, fmaf(e3, h3.z, acc.z))));
        acc.w = fmaf(e0, h0.w, fmaf(e1, h1.w, fmaf(e2, h2.w, fmaf(e3, h3.w, acc.w))));
    }
    for (; j < end; j += 2) {
        int s = g_csr[j];
        float e = __expf(lrelu(g_as[s * 8 + head] + ad));
        den += e;
        float4 hv = *(const float4*)&g_h[s * 64 + c4];
        acc.x = fmaf(e, hv.x, acc.x);
        acc.y = fmaf(e, hv.y, acc.y);
        acc.z = fmaf(e, hv.z, acc.z);
        acc.w = fmaf(e, hv.w, acc.w);
    }

    // combine halves (all 32 lanes converged here)
    den   += __shfl_xor_sync(0xffffffffu, den,   16);
    acc.x += __shfl_xor_sync(0xffffffffu, acc.x, 16);
    acc.y += __shfl_xor_sync(0xffffffffu, acc.y, 16);
    acc.z += __shfl_xor_sync(0xffffffffu, acc.z, 16);
    acc.w += __shfl_xor_sync(0xffffffffu, acc.w, 16);

    if (half == 0) {
        float inv = 1.f / (den + 1e-16f);
        float4 bv = *(const float4*)&bias[c4];
        float4 ov;
        ov.x = bv.x + acc.x * inv;
        ov.y = bv.y + acc.y * inv;
        ov.z = bv.z + acc.z * inv;
        ov.w = bv.w + acc.w * inv;
        *(float4*)&out[n * 64 + c4] = ov;

        float4 wr = *(const float4*)&wrel[c4];
        float4 wq = *(const float4*)&wroot[c4];
        float vr = ov.x * wr.x + ov.y * wr.y + ov.z * wr.z + ov.w * wr.w;
        float vq = ov.x * wq.x + ov.y * wq.y + ov.z * wq.z + ov.w * wq.w;
        #pragma unroll
        for (int off = 8; off; off >>= 1) {
            vr += __shfl_xor_sync(0x0000ffffu, vr, off);
            vq += __shfl_xor_sync(0x0000ffffu, vq, off);
        }
        if (hl == 0) {
            g_p[n]     = vr;
            g_score[n] = brel[0] + vq;
        }
    }
}

// ---------------- K7: score aggregation via CSR + fused exp/gden ----------------
__global__ void k7_score_gexp()
{
    int warp = threadIdx.x >> 5, lane = threadIdx.x & 31;
    int n = blockIdx.x * 8 + warp;
    if (n >= N_NODES) return;
    int beg = g_offs[n], end = g_offs[n + 1];
    float acc = 0.f;
    for (int j = beg + lane; j < end; j += 32) acc += g_p[g_csr[j]];
    #pragma unroll
    for (int off = 16; off; off >>= 1) acc += __shfl_xor_sync(0xffffffffu, acc, off);
    if (lane == 0) {
        float ex = __expf(g_score[n] + acc);   // scores O(±10): unshifted exp safe
        g_score[n] = ex;
        atomicAdd(&g_gden[g_batch[n]], ex);
    }
}

// ---------------- K10: pooled output, 8 nodes/thread w/ register accumulation ----------------
__global__ void k10_gpool(const float* __restrict__ out, float* __restrict__ gout)
{
    int t = blockIdx.x * blockDim.x + threadIdx.x;   // 100000 threads
    if (t >= 100000) return;
    int q   = t & 15;
    int n0  = (t >> 4) * 8;

    float4 acc = make_float4(0.f, 0.f, 0.f, 0.f);
    int curg = g_batch[n0];
    float inv = 1.f / (g_gden[curg] + 1e-16f);
    #pragma unroll
    for (int i = 0; i < 8; i++) {
        int n = n0 + i;
        int g = g_batch[n];
        if (g != curg) {
            red_add_v4(&gout[curg * 64 + q * 4], acc);
            acc = make_float4(0.f, 0.f, 0.f, 0.f);
            curg = g;
            inv = 1.f / (g_gden[curg] + 1e-16f);
        }
        float s = g_score[n] * inv;
        float4 v = *(const float4*)&out[(long)n * 64 + q * 4];
        acc.x = fmaf(v.x, s, acc.x);
        acc.y = fmaf(v.y, s, acc.y);
        acc.z = fmaf(v.z, s, acc.z);
        acc.w = fmaf(v.w, s, acc.w);
    }
    red_add_v4(&gout[curg * 64 + q * 4], acc);
}

// ---------------- launch ----------------
extern "C" void kernel_launch(void* const* d_in, const int* in_sizes, int n_in,
                              void* d_out, int out_size)
{
    const float* x = 0; const void* ei = 0; const void* batch = 0;
    const float* W = 0; const float* brel = 0;
    const float* f64s[5] = {0,0,0,0,0};
    int n64 = 0;
    for (int i = 0; i < n_in; i++) {
        long long sz = in_sizes[i];
        if      (sz == (long long)N_NODES * IN_F) x     = (const float*)d_in[i];
        else if (sz == (long long)2 * N_EDGES)    ei    = d_in[i];
        else if (sz == N_NODES)                   batch = d_in[i];
        else if (sz == IN_F * OUT_F)              W     = (const float*)d_in[i];
        else if (sz == 1)                         brel  = (const float*)d_in[i];
        else if (sz == OUT_F && n64 < 5)          f64s[n64++] = (const float*)d_in[i];
    }
    const float* asrc  = f64s[0];
    const float* adst  = f64s[1];
    const float* bias  = f64s[2];
    const float* wrel  = f64s[3];
    const float* wroot = f64s[4];

    float* out  = (float*)d_out;
    float* gout = out + (long)N_NODES * OUT_F;

    k0_nodes<<<(N_NODES + 255) / 256, 256>>>(batch);              // 1
    k_hist<<<(N_EDGES + 255) / 256, 256>>>(ei);                   // 2
    k_scan1<<<SCAN_BLOCKS, 1024>>>();                             // 3
    k1_gemm<<<(N_NODES + 63) / 64, 256>>>(x, W, asrc, adst);      // 4 <- ncu capture slot
    k_scan3<<<(N_NODES + 255) / 256, 256>>>(gout);                // 5
    k_fill<<<(N_EDGES + 255) / 256, 256>>>(ei);                   // 6
    k_agg<<<(N_NODES + 7) / 8, 256>>>(out, bias, wrel, brel, wroot); // 7
    k7_score_gexp<<<(N_NODES + 7) / 8, 256>>>();                  // 8
    k10_gpool<<<(100000 + 255) / 256, 256>>>(out, gout);          // 9
}